// round 17
// baseline (speedup 1.0000x reference)
#include <cuda_runtime.h>
#include <cuda_bf16.h>

// PEPS 6x6, D=4, phys=2, batch=1024. Row-sweep exact contraction, snake order.
// R17: NT=256, 2 CTAs/SM (128 regs/thread). Interior tile = m4 x n16 per
// thread -> x read ONCE per step (old m4n8 read it twice). Swizzles, st5
// remap, fused head/tail, shift-only staging all carried over.

#define NT 256

typedef unsigned long long u64;

__device__ __forceinline__ u64 pk(float v) {
    u64 r;
    asm("mov.b64 %0, {%1, %1};" : "=l"(r) : "f"(v));
    return r;
}
__device__ __forceinline__ void fma2(u64& d, u64 a, u64 b) {
    asm("fma.rn.f32x2 %0, %1, %2, %0;" : "+l"(d) : "l"(a), "l"(b));
}
__device__ __forceinline__ float2 upk(u64 v) {
    float2 r;
    asm("mov.b64 {%0, %1}, %2;" : "=f"(r.x), "=f"(r.y) : "l"(v));
    return r;
}

// Scalar boundary step, compile-time shapes.
template <int F, int K, int N, int PU, int UD, int SRIN>
__device__ __forceinline__ void step_b(
    float* __restrict__ W, const float* __restrict__ A, int tid)
{
    constexpr int TOTAL = N * F;
    constexpr int NOUT = (TOTAL + NT - 1) / NT;
    float accl[NOUT];
    int cnt = 0;
    for (int o = tid; o < TOTAL; o += NT) {
        const int n = o / F;
        const int m = o - n * F;
        const int dp = m / PU;
        const int ur = m - dp * PU;
        const int inb = dp * UD * PU + ur;
        float s = 0.f;
#pragma unroll
        for (int k = 0; k < K; ++k) {
            const int rin = k / UD;
            const int u = k - rin * UD;
            s = fmaf(W[inb + rin * SRIN + u * PU], A[k * N + n], s);
        }
        accl[cnt++] = s;
    }
    __syncthreads();
    cnt = 0;
    for (int o = tid; o < TOTAL; o += NT) {
        const int n = o / F;
        const int m = o - n * F;
        W[n * F + m] = accl[cnt++];
    }
    __syncthreads();
}

// Vectorized boundary step for m-contiguous inputs. NPG = n's per thread.
template <int F, int K, int N, int PU, int UD, int SRIN>
__device__ __forceinline__ void step_bv(
    float* __restrict__ W, const float* __restrict__ A, int tid)
{
    constexpr int NV = F / 4;              // m-vecs
    constexpr int G = NT / NV;             // n-groups (>=1)
    constexpr int NPG = N / G;             // n's per thread
    static_assert(NPG >= 1 && NPG <= 8, "step_bv tile");
    const int g = (G == 1) ? 0 : (tid / NV);
    const int tv = (G == 1) ? tid : (tid - g * NV);
    const int mb = tv * 4;
    const int dp = mb / PU;
    const int ur = mb - dp * PU;
    const int inb = dp * UD * PU + ur;
    const int n0 = g * NPG;

    u64 acc[NPG][2];
#pragma unroll
    for (int n = 0; n < NPG; ++n) { acc[n][0] = 0ull; acc[n][1] = 0ull; }

#pragma unroll
    for (int k = 0; k < K; ++k) {
        const int off = (k / UD) * SRIN + (k % UD) * PU;
        const ulonglong2 xv = *(const ulonglong2*)(W + inb + off);
#pragma unroll
        for (int n = 0; n < NPG; ++n) {
            const u64 a2 = pk(A[k * N + n0 + n]);
            fma2(acc[n][0], xv.x, a2);
            fma2(acc[n][1], xv.y, a2);
        }
    }
    __syncthreads();
#pragma unroll
    for (int n = 0; n < NPG; ++n) {
        ulonglong2 o;
        o.x = acc[n][0];
        o.y = acc[n][1];
        *(ulonglong2*)(W + (n0 + n) * F + mb) = o;
    }
    __syncthreads();
}

// Interior steps 0..4: F=1024, N=16, Pu = 1<<PSH >= 4. m4 x n16 per thread.
// XOR bank swizzles: 1: idx^(((idx>>6)&3)<<4)  2: idx^(((idx>>5)&3)<<2)
// Per k per thread: 1 x LDS.128 (read ONCE - no n-group duplication),
// 4 broadcast A LDS.128, 16 pk movs (ALU), 32 FFMA2.
template <int K, int PSH, int SWZI, int SWZO>
__device__ __forceinline__ void step_fast_vec(
    float* __restrict__ W, const float* __restrict__ A, int tid)
{
    const int mb = tid << 2;               // m-vec base, tid = 0..255
    const int dp = mb >> PSH;
    const int ur = mb & ((1 << PSH) - 1);
    const int inb = (dp << (PSH + 2)) + ur;

    const int si = (SWZI == 1) ? (dp & 3) : (SWZI == 2) ? ((dp >> 1) & 3) : 0;
    const int so = (SWZO == 1) ? (((mb >> 6) & 3) << 4)
                 : (SWZO == 2) ? (((mb >> 5) & 3) << 2) : 0;

    u64 acc[16][2];
#pragma unroll
    for (int n = 0; n < 16; ++n) { acc[n][0] = 0ull; acc[n][1] = 0ull; }

#pragma unroll
    for (int k = 0; k < K; ++k) {
        const int off = (k >> 2) * 4096 + (((k & 3) ^ si) << PSH);
        const ulonglong2 xv = *(const ulonglong2*)(W + inb + off);
#pragma unroll
        for (int q = 0; q < 4; ++q) {
            const float4 a4 = *(const float4*)(A + k * 16 + q * 4);
            const float av[4] = { a4.x, a4.y, a4.z, a4.w };
#pragma unroll
            for (int j = 0; j < 4; ++j) {
                const u64 a2 = pk(av[j]);
                fma2(acc[q * 4 + j][0], xv.x, a2);
                fma2(acc[q * 4 + j][1], xv.y, a2);
            }
        }
    }

    __syncthreads();
#pragma unroll
    for (int n = 0; n < 16; ++n) {
        ulonglong2 o;
        o.x = acc[n][0];
        o.y = acc[n][1];
        *(ulonglong2*)(W + ((n * 1024 + mb) ^ so)) = o;
    }
    __syncthreads();
}

// Interior step 5: F=1024, N=4, K=16 (layout rin*4096 + m*4 + u).
// 4 m-slots per thread at stride 256: x LDS.128 at 16B*lane stride -> clean.
__device__ __forceinline__ void step_fast_last(
    float* __restrict__ W, const float* __restrict__ A, int tid)
{
    u64 acc[4][2];
#pragma unroll
    for (int j = 0; j < 4; ++j) { acc[j][0] = 0ull; acc[j][1] = 0ull; }

#pragma unroll
    for (int rin = 0; rin < 4; ++rin) {
        float4 xv[4];
#pragma unroll
        for (int j = 0; j < 4; ++j)
            xv[j] = *(const float4*)(W + (tid + j * 256) * 4 + rin * 4096);
#pragma unroll
        for (int u = 0; u < 4; ++u) {
            const ulonglong2 a2 = *(const ulonglong2*)(A + (rin * 4 + u) * 4);
#pragma unroll
            for (int j = 0; j < 4; ++j) {
                const float xs = (u == 0) ? xv[j].x : (u == 1) ? xv[j].y
                               : (u == 2) ? xv[j].z : xv[j].w;
                const u64 p = pk(xs);
                fma2(acc[j][0], p, a2.x);
                fma2(acc[j][1], p, a2.y);
            }
        }
    }
    __syncthreads();
#pragma unroll
    for (int j = 0; j < 4; ++j) {
        const int m = tid + j * 256;
        const float2 v01 = upk(acc[j][0]);
        const float2 v23 = upk(acc[j][1]);
        W[0 * 1024 + m] = v01.x;
        W[1 * 1024 + m] = v01.y;
        W[2 * 1024 + m] = v23.x;
        W[3 * 1024 + m] = v23.y;
    }
    __syncthreads();
}

__global__ __launch_bounds__(NT, 2)
void peps_amp_kernel(const int* __restrict__ x, const float* __restrict__ T,
                     float* __restrict__ out)
{
    extern __shared__ float smem[];
    float* W = smem;                               // [0, 16384)
    float* As = smem + 16384;                      // 36 * 256 = 9216 floats
    int* spins = (int*)(smem + 16384 + 9216);      // 36 (+ pad)

    const int b = blockIdx.x;
    const int tid = threadIdx.x;

    if (tid < 36) spins[tid] = x[b * 36 + tid];
    __syncthreads();

    // Stage ALL 36 site matrices: As[(i*6+st)*256 + k*N + n],
    // k = rin*ud + u, n = rout*dd + d. Shift arithmetic only.
    for (int site = tid; site < 36 * 8; site += NT) {
        const int sidx = site >> 3;
        const int chunk = site & 7;
        const int i = sidx / 6;
        const int st = sidx - i * 6;
        const int udsh = (i == 0) ? 0 : 2;
        const int ddsh = (i == 5) ? 0 : 2;
        const int rish = (st == 0) ? 0 : 2;
        const int rosh = (st == 5) ? 0 : 2;
        const int nsh = rosh + ddsh;
        const int kn = 1 << (udsh + rish + nsh);
        const bool l2r = ((i & 1) == 0);
        const int jc = l2r ? st : (5 - st);
        const int s = spins[i * 6 + jc];
        const float* Tb = T + (size_t)((i * 6 + jc) * 2 + s) * 256;
        const int hi = min(kn, chunk * 32 + 32);
        for (int idx = chunk * 32; idx < hi; ++idx) {
            const int k = idx >> nsh;
            const int n = idx & ((1 << nsh) - 1);
            const int rin = k >> udsh;
            const int u = k & ((1 << udsh) - 1);
            const int rout = n >> ddsh;
            const int d = n & ((1 << ddsh) - 1);
            const int r = l2r ? rout : rin;
            const int l = l2r ? rin : rout;
            As[sidx * 256 + idx] = Tb[u * 64 + r * 16 + d * 4 + l];
        }
    }
    __syncthreads();

    // ---- Row 0 head: st0..st2 fused (direct evaluation of 256 outputs) ----
    {
        const float* A0 = As;
        const float* A1 = As + 256;
        const float* A2 = As + 512;
        const int d0 = tid & 3;
        const int d1 = (tid >> 2) & 3;
        const int n2 = tid >> 4;                   // (r2,d2)
        float s = 0.f;
#pragma unroll
        for (int r1 = 0; r1 < 4; ++r1) {
            float t1 = 0.f;
#pragma unroll
            for (int r0 = 0; r0 < 4; ++r0)
                t1 = fmaf(A0[r0 * 4 + d0], A1[r0 * 16 + r1 * 4 + d1], t1);
            s = fmaf(t1, A2[r1 * 16 + n2], s);
        }
        W[tid] = s;
        __syncthreads();
    }
    // ---- Row 0 st3..st5 ----
    step_b <64,   4, 16, 1, 1, 64  >(W, As + 3 * 256, tid);
    step_bv<256,  4, 16, 1, 1, 256 >(W, As + 4 * 256, tid);
    step_bv<1024, 4, 4,  1, 1, 1024>(W, As + 5 * 256, tid);

    // ---- Rows 1..4 (interior, swizzled) ----
    for (int i = 1; i <= 4; ++i) {
        const float* A = As + i * 6 * 256;
        step_fast_vec<4, 10, 0, 0>(W, A + 0 * 256, tid);
        step_fast_vec<16, 8, 0, 0>(W, A + 1 * 256, tid);
        step_fast_vec<16, 6, 0, 1>(W, A + 2 * 256, tid);   // out: swz1
        step_fast_vec<16, 4, 1, 2>(W, A + 3 * 256, tid);   // in: swz1, out: swz2
        step_fast_vec<16, 2, 2, 0>(W, A + 4 * 256, tid);   // in: swz2
        step_fast_last(W, A + 5 * 256, tid);
    }

    // ---- Row 5 (ud=4, dd=1, R->L) ----
    {
        const float* A = As + 5 * 6 * 256;
        step_bv<1024, 4,  4, 1024, 4, 4096>(W, A + 0 * 256, tid);
        step_b<256, 16,  4, 256,  4, 1024>(W, A + 1 * 256, tid);
        step_b<64,  16,  4, 64,   4, 256 >(W, A + 2 * 256, tid);
        step_b<16,  16,  4, 16,   4, 64  >(W, A + 3 * 256, tid);
        // st4 + st5 fused: 16 threads compute st4's outputs, warp-reduce vs A5.
        if (tid < 32) {
            const float* A4 = A + 4 * 256;
            const float* A5 = A + 5 * 256;
            float v = 0.f;
            if (tid < 16) {
                const int n = tid >> 2;
                const int m = tid & 3;
                float s = 0.f;
#pragma unroll
                for (int k = 0; k < 16; ++k)
                    s = fmaf(W[m + (k >> 2) * 16 + (k & 3) * 4], A4[k * 4 + n], s);
                v = s * A5[tid];
            }
#pragma unroll
            for (int o = 8; o; o >>= 1)
                v += __shfl_down_sync(0xFFFFFFFFu, v, o);
            if (tid == 0) out[b] = v;
        }
    }
}

extern "C" void kernel_launch(void* const* d_in, const int* in_sizes, int n_in,
                              void* d_out, int out_size)
{
    const int T_ELEMS = 6 * 6 * 2 * 4 * 4 * 4 * 4;   // 73728
    const int* x;
    const float* T;
    if (in_sizes[0] == T_ELEMS) {
        T = (const float*)d_in[0];
        x = (const int*)d_in[1];
    } else {
        x = (const int*)d_in[0];
        T = (const float*)d_in[1];
    }

    const int smem_bytes = (16384 + 9216 + 64) * (int)sizeof(float);
    cudaFuncSetAttribute(peps_amp_kernel,
                         cudaFuncAttributeMaxDynamicSharedMemorySize, smem_bytes);
    cudaFuncSetAttribute(peps_amp_kernel,
                         cudaFuncAttributePreferredSharedMemoryCarveout, 100);

    peps_amp_kernel<<<out_size, NT, smem_bytes>>>(x, T, (float*)d_out);
}